// round 15
// baseline (speedup 1.0000x reference)
#include <cuda_runtime.h>
#include <cuda_fp16.h>
#include <cstdint>

#define D_MODEL 2048
#define NUM_EXPERTS 64
#define M_TILE 128
#define KC 64
#define T_CHUNKS (D_MODEL / KC)    // 32
#define NTHREADS 256
#define AS 72                       // row stride (halfs) = 144B == 16 mod 128 -> ldmatrix conflict-free
#define SLICE_LEV_BYTES (32 * AS * 2)        // 4608 : one m-group, one level
#define SLICE_BYTES (2 * SLICE_LEV_BYTES)    // 9216
#define STAGE_BYTES (4 * SLICE_BYTES)        // 36864
#define SMEM_BYTES (2 * STAGE_BYTES)         // 73728 (logits 36864 fits)
#define LSTRIDE 72

// B fragments pre-packed: idx = ((((c*2+wn)*4+ks)*2+lev)*4+nf)*32+lane (uint2)
//   n = wn*32 + nf*8 + lane/4 ; k0 = c*64 + ks*16 + (lane&3)*2
__device__ __align__(16) uint2 g_wf[T_CHUNKS * 2 * 4 * 2 * 4 * 32];

__global__ void prep_w(const float* __restrict__ w) {
    const int idx = blockIdx.x * blockDim.x + threadIdx.x;   // 65536
    const int lane = idx & 31;
    const int nf   = (idx >> 5) & 3;
    const int lev  = (idx >> 7) & 1;
    const int ks   = (idx >> 8) & 3;
    const int wn   = (idx >> 10) & 1;
    const int c    = idx >> 11;

    const int n  = wn * 32 + nf * 8 + (lane >> 2);
    const int k0 = c * KC + ks * 16 + (lane & 3) * 2;

    const float* row = w + (size_t)n * D_MODEL;
    float2 va = *reinterpret_cast<const float2*>(row + k0);
    float2 vb = *reinterpret_cast<const float2*>(row + k0 + 8);

    float v[4] = {va.x, va.y, vb.x, vb.y};
    __half h[4];
#pragma unroll
    for (int j = 0; j < 4; j++) {
        __half h0 = __float2half_rn(v[j]);
        h[j] = lev ? __float2half_rn(v[j] - __half2float(h0)) : h0;
    }
    __half2 lo = __halves2half2(h[0], h[1]);
    __half2 hi = __halves2half2(h[2], h[3]);
    uint2 o;
    o.x = *reinterpret_cast<uint32_t*>(&lo);
    o.y = *reinterpret_cast<uint32_t*>(&hi);
    g_wf[idx] = o;
}

__device__ __forceinline__ uint32_t smem_u32(const void* p) {
    uint32_t a;
    asm("{ .reg .u64 t; cvta.to.shared.u64 t, %1; cvt.u32.u64 %0, t; }" : "=r"(a) : "l"(p));
    return a;
}
__device__ __forceinline__ void ldmatrix_x4(uint32_t* r, uint32_t addr) {
    asm volatile("ldmatrix.sync.aligned.m8n8.x4.shared.b16 {%0,%1,%2,%3}, [%4];"
                 : "=r"(r[0]), "=r"(r[1]), "=r"(r[2]), "=r"(r[3]) : "r"(addr));
}
__device__ __forceinline__ void mma_f32(float* d, const uint32_t* a, uint2 b) {
    asm volatile(
        "mma.sync.aligned.m16n8k16.row.col.f32.f16.f16.f32 "
        "{%0,%1,%2,%3}, {%4,%5,%6,%7}, {%8,%9}, {%0,%1,%2,%3};"
        : "+f"(d[0]), "+f"(d[1]), "+f"(d[2]), "+f"(d[3])
        : "r"(a[0]), "r"(a[1]), "r"(a[2]), "r"(a[3]), "r"(b.x), "r"(b.y));
}
__device__ __forceinline__ void mma_f16(uint32_t* d, const uint32_t* a, uint2 b) {
    asm volatile(
        "mma.sync.aligned.m16n8k16.row.col.f16.f16.f16.f16 "
        "{%0,%1}, {%2,%3,%4,%5}, {%6,%7}, {%0,%1};"
        : "+r"(d[0]), "+r"(d[1])
        : "r"(a[0]), "r"(a[1]), "r"(a[2]), "r"(a[3]), "r"(b.x), "r"(b.y));
}

__global__ void __launch_bounds__(NTHREADS, 2) router_mma(
    const float* __restrict__ x,
    const float* __restrict__ bias,
    float* __restrict__ out,
    int n_rows)
{
    extern __shared__ __align__(16) char smem[];
    const uint32_t sbase = smem_u32(smem);

    const int tid = threadIdx.x;
    const int wid = tid >> 5;
    const int lane = tid & 31;
    const int wm = wid & 3;        // m-group: rows 32*wm..+31
    const int wn = wid >> 2;       // n-group: experts 32*wn..+31
    const long long row0 = (long long)blockIdx.x * M_TILE;

    const int xri = lane >> 3;        // 0..3
    const int xc4 = (lane & 7) * 4;   // float col within 32-col k-half

    const float* xwb = x + (row0 + 32 * wm + 16 * wn) * D_MODEL;
    const uint32_t mslice0 = sbase + wm * SLICE_BYTES;

    float acc[2][4][4];
    uint32_t acch[2][4][2];
#pragma unroll
    for (int mt = 0; mt < 2; mt++)
#pragma unroll
        for (int nf = 0; nf < 4; nf++) {
#pragma unroll
            for (int j = 0; j < 4; j++) acc[mt][nf][j] = 0.0f;
            acch[mt][nf][0] = 0u;
            acch[mt][nf][1] = 0u;
        }

    float4 xv[4];

    // h selects k sub-range [32h, 32h+32) of the 64-k chunk
    auto loadg_half = [&](int c, int h) {
        const int k0 = c * KC + 32 * h;
#pragma unroll
        for (int i = 0; i < 4; i++)
            xv[i] = *reinterpret_cast<const float4*>(
                xwb + (long long)(4 * i + xri) * D_MODEL + k0 + xc4);
    };

    auto stores_half = [&](int buf, int h) {
        const uint32_t A0 = mslice0 + buf * STAGE_BYTES;
        const uint32_t A1 = A0 + SLICE_LEV_BYTES;
#pragma unroll
        for (int i = 0; i < 4; i++) {
            float4 v = xv[i];
            __half2 h0a = __floats2half2_rn(v.x, v.y);
            __half2 h0b = __floats2half2_rn(v.z, v.w);
            float r0 = v.x - __half2float(h0a.x);
            float r1 = v.y - __half2float(h0a.y);
            float r2 = v.z - __half2float(h0b.x);
            float r3 = v.w - __half2float(h0b.y);
            __half2 h1a = __floats2half2_rn(r0, r1);
            __half2 h1b = __floats2half2_rn(r2, r3);

            const uint32_t o = ((16 * wn + 4 * i + xri) * AS + 32 * h + xc4) * 2;
            asm volatile("st.shared.v2.b32 [%0], {%1, %2};" ::
                "r"(A0 + o), "r"(*reinterpret_cast<uint32_t*>(&h0a)),
                "r"(*reinterpret_cast<uint32_t*>(&h0b)) : "memory");
            asm volatile("st.shared.v2.b32 [%0], {%1, %2};" ::
                "r"(A1 + o), "r"(*reinterpret_cast<uint32_t*>(&h1a)),
                "r"(*reinterpret_cast<uint32_t*>(&h1b)) : "memory");
        }
    };

    const int lrow = ((lane >> 3) & 1) * 8 + (lane & 7);
    const int lkof = (lane >> 4) * 8;

    auto compute_ks = [&](int c, int buf, int ks) {
        const uint32_t Ab = mslice0 + buf * STAGE_BYTES;
        uint2 b[8];
        const uint2* Wf = g_wf + (((size_t)(c * 2 + wn) * 4 + ks) * 2) * 4 * 32;
#pragma unroll
        for (int q = 0; q < 8; q++)
            b[q] = Wf[q * 32 + lane];

        uint32_t a0[2][4], a1[2][4];
#pragma unroll
        for (int mt = 0; mt < 2; mt++) {
            const uint32_t ro = ((mt * 16 + lrow) * AS + ks * 16 + lkof) * 2;
            ldmatrix_x4(a0[mt], Ab + ro);
            ldmatrix_x4(a1[mt], Ab + SLICE_LEV_BYTES + ro);
        }

        // x0*w0 : fp32 acc
#pragma unroll
        for (int mt = 0; mt < 2; mt++)
#pragma unroll
            for (int nf = 0; nf < 4; nf++)
                mma_f32(acc[mt][nf], a0[mt], b[nf]);
        // x0*w1 : fp16 acc
#pragma unroll
        for (int mt = 0; mt < 2; mt++)
#pragma unroll
            for (int nf = 0; nf < 4; nf++)
                mma_f16(acch[mt][nf], a0[mt], b[4 + nf]);
        // x1*w0 : fp16 acc
#pragma unroll
        for (int mt = 0; mt < 2; mt++)
#pragma unroll
            for (int nf = 0; nf < 4; nf++)
                mma_f16(acch[mt][nf], a1[mt], b[nf]);
    };

    // ---- prologue ----
    loadg_half(0, 0);
    stores_half(0, 0);
    loadg_half(0, 1);
    stores_half(0, 1);
    __syncthreads();

    // ---- main loop: 1 barrier per 64-k chunk ----
#pragma unroll 1
    for (int c = 0; c < T_CHUNKS; ++c) {
        const int buf = c & 1;
        const int nbuf = (c + 1) & 1;
        const bool more = (c + 1 < T_CHUNKS);
        const int cn = more ? c + 1 : c;

        loadg_half(cn, 0);
        compute_ks(c, buf, 0);
        compute_ks(c, buf, 1);
        if (more) stores_half(nbuf, 0);
        loadg_half(cn, 1);
        compute_ks(c, buf, 2);
        compute_ks(c, buf, 3);
        if (more) stores_half(nbuf, 1);
        __syncthreads();
    }

    // ---- epilogue: merge fp16 residual acc, scatter, top-2 ----
    float* logits = reinterpret_cast<float*>(smem);
#pragma unroll
    for (int mt = 0; mt < 2; mt++)
#pragma unroll
        for (int nf = 0; nf < 4; nf++) {
            __half2 hlo = *reinterpret_cast<__half2*>(&acch[mt][nf][0]);
            __half2 hhi = *reinterpret_cast<__half2*>(&acch[mt][nf][1]);
            float f0 = acc[mt][nf][0] + __half2float(hlo.x);
            float f1 = acc[mt][nf][1] + __half2float(hlo.y);
            float f2 = acc[mt][nf][2] + __half2float(hhi.x);
            float f3 = acc[mt][nf][3] + __half2float(hhi.y);
            const int r = 32 * wm + 16 * mt + (lane >> 2);
            const int col = 32 * wn + nf * 8 + (lane & 3) * 2;
            *reinterpret_cast<float2*>(logits + r * LSTRIDE + col) = make_float2(f0, f1);
            *reinterpret_cast<float2*>(logits + (r + 8) * LSTRIDE + col) = make_float2(f2, f3);
        }
    __syncthreads();

    if (tid < M_TILE) {
        const int r = tid;
        const float* lrw = logits + r * LSTRIDE;
        float v0 = -3.0e38f, v1 = -3.0e38f;
        int i0 = 0, i1 = 0;
#pragma unroll
        for (int e = 0; e < NUM_EXPERTS; e++) {
            float l = lrw[e] + __ldg(&bias[e]);
            if (l > v0) { v1 = v0; i1 = i0; v0 = l; i0 = e; }
            else if (l > v1) { v1 = l; i1 = e; }
        }
        float Z = 0.0f;
#pragma unroll
        for (int e = 0; e < NUM_EXPERTS; e++) {
            float l = lrw[e] + __ldg(&bias[e]);
            Z += __expf(l - v0);
        }
        float q0 = 1.0f / Z;
        float q1 = __expf(v1 - v0) / Z;
        float s = q0 + q1 + 1e-8f;
        long long gr = row0 + r;
        out[gr * 2 + 0] = q0 / s;
        out[gr * 2 + 1] = q1 / s;
        float* ido = out + (long long)n_rows * 2;
        ido[gr * 2 + 0] = (float)i0;
        ido[gr * 2 + 1] = (float)i1;
    }
}

extern "C" void kernel_launch(void* const* d_in, const int* in_sizes, int n_in,
                              void* d_out, int out_size) {
    const float* x    = (const float*)d_in[0];
    const float* gw   = (const float*)d_in[1];
    const float* bias = (const float*)d_in[2];
    float* out = (float*)d_out;
    int n_rows = in_sizes[0] / D_MODEL;   // 32768

    cudaFuncSetAttribute(router_mma, cudaFuncAttributeMaxDynamicSharedMemorySize, SMEM_BYTES);

    prep_w<<<(T_CHUNKS * 2 * 4 * 2 * 4 * 32) / 256, 256>>>(gw);
    router_mma<<<n_rows / M_TILE, NTHREADS, SMEM_BYTES>>>(x, bias, out, n_rows);
}

// round 16
// speedup vs baseline: 1.1668x; 1.1668x over previous
#include <cuda_runtime.h>
#include <cuda_fp16.h>
#include <cstdint>

#define D_MODEL 2048
#define NUM_EXPERTS 64
#define M_TILE 128
#define KC 32
#define T_CHUNKS (D_MODEL / KC)    // 64
#define NTHREADS 256
#define SMEM_BYTES (128 * 72 * 4)  // logits only
#define LSTRIDE 72

// B fragments pre-packed with the SAME k-permutation as the direct A loads:
// idx = ((((c*2+wn)*2+ks)*2+lev)*4+nf)*32 + lane   (uint2)
//   n = wn*32 + nf*8 + lane/4 ; g0 = c*32 + ks*16 + (lane&3)*4
//   .x = half2(w[n][g0], w[n][g0+1])   -> k-lo slots
//   .y = half2(w[n][g0+2], w[n][g0+3]) -> k-hi slots
__device__ __align__(16) uint2 g_wf[T_CHUNKS * 2 * 2 * 2 * 4 * 32];

__global__ void prep_w(const float* __restrict__ w) {
    const int idx = blockIdx.x * blockDim.x + threadIdx.x;   // 65536
    const int lane = idx & 31;
    const int nf   = (idx >> 5) & 3;
    const int lev  = (idx >> 7) & 1;
    const int ks   = (idx >> 8) & 1;
    const int wn   = (idx >> 9) & 1;
    const int c    = idx >> 10;

    const int n  = wn * 32 + nf * 8 + (lane >> 2);
    const int g0 = c * KC + ks * 16 + (lane & 3) * 4;

    float4 v = *reinterpret_cast<const float4*>(w + (size_t)n * D_MODEL + g0);
    float f[4] = {v.x, v.y, v.z, v.w};
    __half h[4];
#pragma unroll
    for (int j = 0; j < 4; j++) {
        __half h0 = __float2half_rn(f[j]);
        h[j] = lev ? __float2half_rn(f[j] - __half2float(h0)) : h0;
    }
    __half2 lo = __halves2half2(h[0], h[1]);
    __half2 hi = __halves2half2(h[2], h[3]);
    uint2 o;
    o.x = *reinterpret_cast<uint32_t*>(&lo);
    o.y = *reinterpret_cast<uint32_t*>(&hi);
    g_wf[idx] = o;
}

__device__ __forceinline__ void mma_f32(float* d, const uint32_t* a, uint2 b) {
    asm volatile(
        "mma.sync.aligned.m16n8k16.row.col.f32.f16.f16.f32 "
        "{%0,%1,%2,%3}, {%4,%5,%6,%7}, {%8,%9}, {%0,%1,%2,%3};"
        : "+f"(d[0]), "+f"(d[1]), "+f"(d[2]), "+f"(d[3])
        : "r"(a[0]), "r"(a[1]), "r"(a[2]), "r"(a[3]), "r"(b.x), "r"(b.y));
}
__device__ __forceinline__ void mma_f16(uint32_t* d, const uint32_t* a, uint2 b) {
    asm volatile(
        "mma.sync.aligned.m16n8k16.row.col.f16.f16.f16.f16 "
        "{%0,%1}, {%2,%3,%4,%5}, {%6,%7}, {%0,%1};"
        : "+r"(d[0]), "+r"(d[1])
        : "r"(a[0]), "r"(a[1]), "r"(a[2]), "r"(a[3]), "r"(b.x), "r"(b.y));
}

__global__ void __launch_bounds__(NTHREADS, 2) router_mma(
    const float* __restrict__ x,
    const float* __restrict__ bias,
    float* __restrict__ out,
    int n_rows)
{
    extern __shared__ __align__(16) float smem_logits[];

    const int tid = threadIdx.x;
    const int wid = tid >> 5;
    const int lane = tid & 31;
    const int wm = wid & 3;        // m-group: rows 32*wm..+31
    const int wn = wid >> 2;       // n-group: experts 32*wn..+31
    const long long row0 = (long long)blockIdx.x * M_TILE;

    // per-lane x row pointers (rows r and r+8 for each mt)
    const float* xr0 = x + (row0 + 32 * wm + (lane >> 2)) * D_MODEL + (lane & 3) * 4;

    float acc[2][4][4];
    uint32_t acch[2][4][2];
#pragma unroll
    for (int mt = 0; mt < 2; mt++)
#pragma unroll
        for (int nf = 0; nf < 4; nf++) {
#pragma unroll
            for (int j = 0; j < 4; j++) acc[mt][nf][j] = 0.0f;
            acch[mt][nf][0] = 0u;
            acch[mt][nf][1] = 0u;
        }

    // xs layout: [mt*2 + rowpair] ; rowpair 0 = row r, 1 = row r+8
    auto loadx = [&](int c, int ks, float4* dst) {
        const int off = c * KC + ks * 16;
#pragma unroll
        for (int mt = 0; mt < 2; mt++) {
            const float* p = xr0 + (long long)(16 * mt) * D_MODEL + off;
            dst[2 * mt]     = *reinterpret_cast<const float4*>(p);
            dst[2 * mt + 1] = *reinterpret_cast<const float4*>(p + 8 * D_MODEL);
        }
    };

    auto compute_half = [&](int c, int ks, const float4* xs) {
        // B frags (L1/L2-resident): lev0 = b[0..3], lev1 = b[4..7]
        uint2 b[8];
        const uint2* Wf = g_wf + (((size_t)(c * 2 + wn) * 2 + ks) * 2) * 4 * 32;
#pragma unroll
        for (int q = 0; q < 8; q++)
            b[q] = Wf[q * 32 + lane];

#pragma unroll
        for (int mt = 0; mt < 2; mt++) {
            float4 f0 = xs[2 * mt];       // row r
            float4 f1 = xs[2 * mt + 1];   // row r+8
            // level 0 fragments (a[0]=r/klo, a[1]=r+8/klo, a[2]=r/khi, a[3]=r+8/khi)
            __half2 p0 = __floats2half2_rn(f0.x, f0.y);
            __half2 p1 = __floats2half2_rn(f1.x, f1.y);
            __half2 p2 = __floats2half2_rn(f0.z, f0.w);
            __half2 p3 = __floats2half2_rn(f1.z, f1.w);
            // residuals -> level 1
            __half2 q0 = __floats2half2_rn(f0.x - __half2float(p0.x), f0.y - __half2float(p0.y));
            __half2 q1 = __floats2half2_rn(f1.x - __half2float(p1.x), f1.y - __half2float(p1.y));
            __half2 q2 = __floats2half2_rn(f0.z - __half2float(p2.x), f0.w - __half2float(p2.y));
            __half2 q3 = __floats2half2_rn(f1.z - __half2float(p3.x), f1.w - __half2float(p3.y));

            uint32_t a0[4] = {*reinterpret_cast<uint32_t*>(&p0), *reinterpret_cast<uint32_t*>(&p1),
                              *reinterpret_cast<uint32_t*>(&p2), *reinterpret_cast<uint32_t*>(&p3)};
            uint32_t a1[4] = {*reinterpret_cast<uint32_t*>(&q0), *reinterpret_cast<uint32_t*>(&q1),
                              *reinterpret_cast<uint32_t*>(&q2), *reinterpret_cast<uint32_t*>(&q3)};

            // x0*w0 : fp32 acc
#pragma unroll
            for (int nf = 0; nf < 4; nf++)
                mma_f32(acc[mt][nf], a0, b[nf]);
            // x0*w1 : fp16 acc
#pragma unroll
            for (int nf = 0; nf < 4; nf++)
                mma_f16(acch[mt][nf], a0, b[4 + nf]);
            // x1*w0 : fp16 acc
#pragma unroll
            for (int nf = 0; nf < 4; nf++)
                mma_f16(acch[mt][nf], a1, b[nf]);
        }
    };

    // ---- warp-independent main loop, half-chunk register prefetch ----
    float4 xA[4], xB[4];
    loadx(0, 0, xA);

#pragma unroll 1
    for (int c = 0; c < T_CHUNKS; ++c) {
        loadx(c, 1, xB);
        compute_half(c, 0, xA);
        if (c + 1 < T_CHUNKS) loadx(c + 1, 0, xA);
        compute_half(c, 1, xB);
    }

    // ---- epilogue: merge fp16 residual acc, scatter, top-2 ----
    float* logits = smem_logits;
#pragma unroll
    for (int mt = 0; mt < 2; mt++)
#pragma unroll
        for (int nf = 0; nf < 4; nf++) {
            __half2 hlo = *reinterpret_cast<__half2*>(&acch[mt][nf][0]);
            __half2 hhi = *reinterpret_cast<__half2*>(&acch[mt][nf][1]);
            float f0 = acc[mt][nf][0] + __half2float(hlo.x);
            float f1 = acc[mt][nf][1] + __half2float(hlo.y);
            float f2 = acc[mt][nf][2] + __half2float(hhi.x);
            float f3 = acc[mt][nf][3] + __half2float(hhi.y);
            const int r = 32 * wm + 16 * mt + (lane >> 2);
            const int col = 32 * wn + nf * 8 + (lane & 3) * 2;
            *reinterpret_cast<float2*>(logits + r * LSTRIDE + col) = make_float2(f0, f1);
            *reinterpret_cast<float2*>(logits + (r + 8) * LSTRIDE + col) = make_float2(f2, f3);
        }
    __syncthreads();

    if (tid < M_TILE) {
        const int r = tid;
        const float* lrw = logits + r * LSTRIDE;
        float v0 = -3.0e38f, v1 = -3.0e38f;
        int i0 = 0, i1 = 0;
#pragma unroll
        for (int e = 0; e < NUM_EXPERTS; e++) {
            float l = lrw[e] + __ldg(&bias[e]);
            if (l > v0) { v1 = v0; i1 = i0; v0 = l; i0 = e; }
            else if (l > v1) { v1 = l; i1 = e; }
        }
        float Z = 0.0f;
#pragma unroll
        for (int e = 0; e < NUM_EXPERTS; e++) {
            float l = lrw[e] + __ldg(&bias[e]);
            Z += __expf(l - v0);
        }
        float q0 = 1.0f / Z;
        float q1 = __expf(v1 - v0) / Z;
        float s = q0 + q1 + 1e-8f;
        long long gr = row0 + r;
        out[gr * 2 + 0] = q0 / s;
        out[gr * 2 + 1] = q1 / s;
        float* ido = out + (long long)n_rows * 2;
        ido[gr * 2 + 0] = (float)i0;
        ido[gr * 2 + 1] = (float)i1;
    }
}

extern "C" void kernel_launch(void* const* d_in, const int* in_sizes, int n_in,
                              void* d_out, int out_size) {
    const float* x    = (const float*)d_in[0];
    const float* gw   = (const float*)d_in[1];
    const float* bias = (const float*)d_in[2];
    float* out = (float*)d_out;
    int n_rows = in_sizes[0] / D_MODEL;   // 32768

    cudaFuncSetAttribute(router_mma, cudaFuncAttributeMaxDynamicSharedMemorySize, SMEM_BYTES);

    prep_w<<<(T_CHUNKS * 2 * 2 * 2 * 4 * 32) / 256, 256>>>(gw);
    router_mma<<<n_rows / M_TILE, NTHREADS, SMEM_BYTES>>>(x, bias, out, n_rows);
}